// round 5
// baseline (speedup 1.0000x reference)
#include <cuda_runtime.h>

// 4-qubit statevector VQC. 128 threads: warps 0-3 build gate data in one
// loop-free distributed pass; warp 0 alone runs the verified R4 amplitude
// chain (20 gather-steps: per layer one sigma-fused 4x4 pair-gate on qubits
// (0,1) and one 4x4 pair-gate on qubits (2,3)).
//
// R5 vs R4: 4-warp prologue (MUFU spread over 4 SMSPs, no loops/predication),
// warp 0 computes the initial product state concurrently with the row build,
// single __syncthreads barriers, predicated output stores.

__global__ void __launch_bounds__(128, 1)
vqc_kernel(const float* __restrict__ psi,
           const float* __restrict__ ring,
           const float* __restrict__ prx,
           const float* __restrict__ pry,
           const float* __restrict__ prz,
           float* __restrict__ out) {
    __shared__ float4 Gs[40];      // fused 2x2 per gate: (g00re,g00im,g01re,g01im)
    __shared__ float4 Rows[160];   // 80 pair-matrix rows x 2 float4
    __shared__ float2 Ps[4];       // (cos(psi/2), sin(psi/2))
    const unsigned FULL = 0xFFFFFFFFu;
    const int l = threadIdx.x;     // 0..127
    const int k = l & 15;

    // ---- warp 0: issue ring loads immediately (latency hidden by build) ----
    float4 rA4, rB4;
    if (l < 32) {
        rA4 = reinterpret_cast<const float4*>(ring)[0];
        rB4 = reinterpret_cast<const float4*>(ring)[1];
    }

    // ---- stage 1 (lanes 0-39): one fused 2x2 gate M = RZ*RY*RX per lane ----
    if (l < 40) {
        float c1, s1, c2, s2, c3, s3;
        __sincosf(0.5f * prx[l], &s1, &c1);
        __sincosf(0.5f * pry[l], &s2, &c2);
        __sincosf(0.5f * prz[l], &s3, &c3);
        float p1 = c2 * c1, p2 = s2 * s1, p3 = s2 * c1, p4 = c2 * s1;
        float g00re =  fmaf(c3, p1,  s3 * p2);
        float g00im =  fmaf(c3, p2, -s3 * p1);
        float g01re = -fmaf(c3, p3,  s3 * p4);
        float g01im =  fmaf(s3, p3, -c3 * p4);
        Gs[l] = make_float4(g00re, g00im, g01re, g01im);
    } else if (l < 44) {
        float s, c;
        __sincosf(0.5f * psi[l - 40], &s, &c);
        Ps[l - 40] = make_float2(c, s);
    }
    __syncthreads();

    // ---- stage 2 (lanes 32-111): one 4x4 pair-matrix row per lane ----
    // row index idx = d*8 + p*4 + r, r=(a,b); G = M_{2p} (x) M_{2p+1}.
    if (l >= 32 && l < 112) {
        int idx = l - 32;
        int d = idx >> 3, w = idx & 7, p = w >> 2, r = w & 3;
        int a = r >> 1, b = r & 1;
        float4 gA = Gs[d * 4 + 2 * p];
        float4 gB = Gs[d * 4 + 2 * p + 1];
        // row a of M: a==0 -> (g00,g01); a==1 -> (-conj(g01), conj(g00))
        float ar0 = a ? -gA.z : gA.x, ai0 = a ?  gA.w : gA.y;
        float ar1 = a ?  gA.x : gA.z, ai1 = a ? -gA.y : gA.w;
        float br0 = b ? -gB.z : gB.x, bi0 = b ?  gB.w : gB.y;
        float br1 = b ?  gB.x : gB.z, bi1 = b ? -gB.y : gB.w;
        float g0r = ar0 * br0 - ai0 * bi0, g0i = ar0 * bi0 + ai0 * br0;
        float g1r = ar0 * br1 - ai0 * bi1, g1i = ar0 * bi1 + ai0 * br1;
        float g2r = ar1 * br0 - ai1 * bi0, g2i = ar1 * bi0 + ai1 * br0;
        float g3r = ar1 * br1 - ai1 * bi1, g3i = ar1 * bi1 + ai1 * br1;
        Rows[idx * 2 + 0] = make_float4(g0r, g0i, g1r, g1i);
        Rows[idx * 2 + 1] = make_float4(g2r, g2i, g3r, g3i);
    }

    // ---- warp 0 concurrently: initial product state with RX(psi) folded ----
    float re = 0.0f, im = 0.0f;
    int sA0 = 0, sA1 = 0, sA2 = 0, sA3 = 0, rAi = 0, rBi = 0;
    if (l < 32) {
        float rr[4][2] = { { rA4.x, rA4.y }, { rA4.z, rA4.w },
                           { rB4.x, rB4.y }, { rB4.z, rB4.w } };
        float vre[4], vim[4];
#pragma unroll
        for (int n = 0; n < 4; n++) {
            int b = (k >> (3 - n)) & 1;
            float2 cs = Ps[n];   // visible: written before the first barrier
            vre[n] =  cs.x * rr[n][b];
            vim[n] = -cs.y * rr[n][b ^ 1];
        }
        float are = vre[0] * vre[1] - vim[0] * vim[1];
        float aim = vre[0] * vim[1] + vim[0] * vre[1];
        float bre = vre[2] * vre[3] - vim[2] * vim[3];
        float bim = vre[2] * vim[3] + vim[2] * vre[3];
        re = are * bre - aim * bim;
        im = are * bim + aim * bre;

        // composed CNOT-ring permutation (verified R2-R4)
        auto perm = [](int j) {
            j = (j & 1) ? (j ^ 8) : j;
            j = (j & 2) ? (j ^ 1) : j;
            j = (j & 4) ? (j ^ 2) : j;
            j = (j & 8) ? (j ^ 4) : j;
            return j;
        };
        sA0 = perm((k & 3) | 0);  sA1 = perm((k & 3) | 4);
        sA2 = perm((k & 3) | 8);  sA3 = perm((k & 3) | 12);
        rAi = (k >> 2) & 3;       rBi = k & 3;
    }
    __syncthreads();
    if (l >= 32) return;   // warps 1-3 done; no barriers past this point

    const int sB0 = (k & 12) | 0, sB1 = (k & 12) | 1;
    const int sB2 = (k & 12) | 2, sB3 = (k & 12) | 3;

    // ---- variational layers: 2 gather-steps per layer (verified R4) ----
#pragma unroll
    for (int d = 0; d < 10; d++) {
        {   // step A: sigma-fused 4x4 on qubits (0,1)
            int base = (d * 8 + rAi) * 2;
            float4 e0 = Rows[base], e1 = Rows[base + 1];
            float x0 = __shfl_sync(FULL, re, sA0), y0 = __shfl_sync(FULL, im, sA0);
            float x1 = __shfl_sync(FULL, re, sA1), y1 = __shfl_sync(FULL, im, sA1);
            float x2 = __shfl_sync(FULL, re, sA2), y2 = __shfl_sync(FULL, im, sA2);
            float x3 = __shfl_sync(FULL, re, sA3), y3 = __shfl_sync(FULL, im, sA3);
            float pr0 = e0.x * x0; pr0 = fmaf(-e0.y, y0, pr0);
            float pr1 = e0.z * x1; pr1 = fmaf(-e0.w, y1, pr1);
            float pr2 = e1.x * x2; pr2 = fmaf(-e1.y, y2, pr2);
            float pr3 = e1.z * x3; pr3 = fmaf(-e1.w, y3, pr3);
            float pi0 = e0.x * y0; pi0 = fmaf(e0.y, x0, pi0);
            float pi1 = e0.z * y1; pi1 = fmaf(e0.w, x1, pi1);
            float pi2 = e1.x * y2; pi2 = fmaf(e1.y, x2, pi2);
            float pi3 = e1.z * y3; pi3 = fmaf(e1.w, x3, pi3);
            re = (pr0 + pr1) + (pr2 + pr3);
            im = (pi0 + pi1) + (pi2 + pi3);
        }
        {   // step B: 4x4 on qubits (2,3)
            int base = (d * 8 + 4 + rBi) * 2;
            float4 e0 = Rows[base], e1 = Rows[base + 1];
            float x0 = __shfl_sync(FULL, re, sB0), y0 = __shfl_sync(FULL, im, sB0);
            float x1 = __shfl_sync(FULL, re, sB1), y1 = __shfl_sync(FULL, im, sB1);
            float x2 = __shfl_sync(FULL, re, sB2), y2 = __shfl_sync(FULL, im, sB2);
            float x3 = __shfl_sync(FULL, re, sB3), y3 = __shfl_sync(FULL, im, sB3);
            float pr0 = e0.x * x0; pr0 = fmaf(-e0.y, y0, pr0);
            float pr1 = e0.z * x1; pr1 = fmaf(-e0.w, y1, pr1);
            float pr2 = e1.x * x2; pr2 = fmaf(-e1.y, y2, pr2);
            float pr3 = e1.z * x3; pr3 = fmaf(-e1.w, y3, pr3);
            float pi0 = e0.x * y0; pi0 = fmaf(e0.y, x0, pi0);
            float pi1 = e0.z * y1; pi1 = fmaf(e0.w, x1, pi1);
            float pi2 = e1.x * y2; pi2 = fmaf(e1.y, x2, pi2);
            float pi3 = e1.z * y3; pi3 = fmaf(e1.w, x3, pi3);
            re = (pr0 + pr1) + (pr2 + pr3);
            im = (pi0 + pi1) + (pi2 + pi3);
        }
    }

    // ---- outputs: |amp[0]|^2, |amp[2]|^2, |amp[15]|^2 (predicated stores) ----
    float prob = fmaf(re, re, im * im);
    if (l == 0)  out[0] = prob;
    if (l == 2)  out[1] = prob;
    if (l == 15) out[2] = prob;
}

extern "C" void kernel_launch(void* const* d_in, const int* in_sizes, int n_in,
                              void* d_out, int out_size) {
    const float* psi  = (const float*)d_in[0];
    const float* ring = (const float*)d_in[1];
    const float* prx  = (const float*)d_in[2];
    const float* pry  = (const float*)d_in[3];
    const float* prz  = (const float*)d_in[4];
    vqc_kernel<<<1, 128>>>(psi, ring, prx, pry, prz, (float*)d_out);
}

// round 6
// speedup vs baseline: 1.0435x; 1.0435x over previous
#include <cuda_runtime.h>

// 4-qubit statevector VQC. 128 threads, ONE barrier.
//  * lanes 32-111 each build one 4x4 pair-matrix row (Kronecker of two fused
//    RZ*RY*RX gates) directly from the params - no intermediate Gs staging,
//    no first barrier.
//  * warp 0 concurrently: loads ring/psi, computes psi sincos on lanes 0-3
//    (broadcast via shfl, no smem), builds the initial product state and the
//    composed CNOT-ring permutation indices.
//  * after the single __syncthreads, warps 1-3 exit; warp 0 runs the verified
//    20-gather-step chain (per layer: sigma-fused 4x4 on qubits (0,1), then
//    4x4 on qubits (2,3)).

__global__ void __launch_bounds__(128, 1)
vqc_kernel(const float* __restrict__ psi,
           const float* __restrict__ ring,
           const float* __restrict__ prx,
           const float* __restrict__ pry,
           const float* __restrict__ prz,
           float* __restrict__ out) {
    __shared__ float4 Rows[160];   // 80 pair-matrix rows x 2 float4
    const unsigned FULL = 0xFFFFFFFFu;
    const int l = threadIdx.x;     // 0..127
    const int k = l & 15;

    float re = 0.0f, im = 0.0f;
    int sA0 = 0, sA1 = 0, sA2 = 0, sA3 = 0, rAi = 0, rBi = 0;

    if (l >= 32) {
        // ---- producers: lanes 32-111 build one Kronecker row each ----
        if (l < 112) {
            int idx = l - 32;                       // 0..79
            int d = idx >> 3, w = idx & 7, p = w >> 2, r = w & 3;
            int a = r >> 1, b = r & 1;
            int iA = d * 4 + 2 * p, iB = iA + 1;

            // fused gate A = RZ*RY*RX (gate iA)
            float c1, s1, c2, s2, c3, s3;
            __sincosf(0.5f * prx[iA], &s1, &c1);
            __sincosf(0.5f * pry[iA], &s2, &c2);
            __sincosf(0.5f * prz[iA], &s3, &c3);
            float p1 = c2 * c1, p2 = s2 * s1, p3 = s2 * c1, p4 = c2 * s1;
            float A00re =  fmaf(c3, p1,  s3 * p2);
            float A00im =  fmaf(c3, p2, -s3 * p1);
            float A01re = -fmaf(c3, p3,  s3 * p4);
            float A01im =  fmaf(s3, p3, -c3 * p4);

            // fused gate B (gate iB)
            __sincosf(0.5f * prx[iB], &s1, &c1);
            __sincosf(0.5f * pry[iB], &s2, &c2);
            __sincosf(0.5f * prz[iB], &s3, &c3);
            p1 = c2 * c1; p2 = s2 * s1; p3 = s2 * c1; p4 = c2 * s1;
            float B00re =  fmaf(c3, p1,  s3 * p2);
            float B00im =  fmaf(c3, p2, -s3 * p1);
            float B01re = -fmaf(c3, p3,  s3 * p4);
            float B01im =  fmaf(s3, p3, -c3 * p4);

            // row a of M: a==0 -> (g00,g01); a==1 -> (-conj(g01), conj(g00))
            float ar0 = a ? -A01re : A00re, ai0 = a ?  A01im : A00im;
            float ar1 = a ?  A00re : A01re, ai1 = a ? -A00im : A01im;
            float br0 = b ? -B01re : B00re, bi0 = b ?  B01im : B00im;
            float br1 = b ?  B00re : B01re, bi1 = b ? -B00im : B01im;

            float g0r = ar0 * br0 - ai0 * bi0, g0i = ar0 * bi0 + ai0 * br0;
            float g1r = ar0 * br1 - ai0 * bi1, g1i = ar0 * bi1 + ai0 * br1;
            float g2r = ar1 * br0 - ai1 * bi0, g2i = ar1 * bi0 + ai1 * br0;
            float g3r = ar1 * br1 - ai1 * bi1, g3i = ar1 * bi1 + ai1 * br1;
            Rows[idx * 2 + 0] = make_float4(g0r, g0i, g1r, g1i);
            Rows[idx * 2 + 1] = make_float4(g2r, g2i, g3r, g3i);
        }
    } else {
        // ---- warp 0: init state + permutation, fully concurrent ----
        float4 rA4 = reinterpret_cast<const float4*>(ring)[0];
        float4 rB4 = reinterpret_cast<const float4*>(ring)[1];

        // psi sincos on lanes 0-3, broadcast by shuffle (no smem)
        float pc = 1.0f, ps = 0.0f;
        float pa = (l < 4) ? psi[l] : 0.0f;
        __sincosf(0.5f * pa, &ps, &pc);

        float rr[4][2] = { { rA4.x, rA4.y }, { rA4.z, rA4.w },
                           { rB4.x, rB4.y }, { rB4.z, rB4.w } };
        float vre[4], vim[4];
#pragma unroll
        for (int n = 0; n < 4; n++) {
            float cn = __shfl_sync(FULL, pc, n);
            float sn = __shfl_sync(FULL, ps, n);
            int b = (k >> (3 - n)) & 1;
            vre[n] =  cn * rr[n][b];
            vim[n] = -sn * rr[n][b ^ 1];
        }
        float are = vre[0] * vre[1] - vim[0] * vim[1];
        float aim = vre[0] * vim[1] + vim[0] * vre[1];
        float bre = vre[2] * vre[3] - vim[2] * vim[3];
        float bim = vre[2] * vim[3] + vim[2] * vre[3];
        re = are * bre - aim * bim;
        im = are * bim + aim * bre;

        // composed CNOT-ring permutation (verified R2-R5)
        auto perm = [](int j) {
            j = (j & 1) ? (j ^ 8) : j;
            j = (j & 2) ? (j ^ 1) : j;
            j = (j & 4) ? (j ^ 2) : j;
            j = (j & 8) ? (j ^ 4) : j;
            return j;
        };
        sA0 = perm((k & 3) | 0);  sA1 = perm((k & 3) | 4);
        sA2 = perm((k & 3) | 8);  sA3 = perm((k & 3) | 12);
        rAi = (k >> 2) & 3;       rBi = k & 3;
    }

    __syncthreads();
    if (l >= 32) return;   // producers done

    const int sB0 = (k & 12) | 0, sB1 = (k & 12) | 1;
    const int sB2 = (k & 12) | 2, sB3 = (k & 12) | 3;

    // ---- variational layers: 2 gather-steps per layer (verified R4/R5) ----
#pragma unroll
    for (int d = 0; d < 10; d++) {
        {   // step A: sigma-fused 4x4 on qubits (0,1)
            int base = (d * 8 + rAi) * 2;
            float4 e0 = Rows[base], e1 = Rows[base + 1];
            float x0 = __shfl_sync(FULL, re, sA0), y0 = __shfl_sync(FULL, im, sA0);
            float x1 = __shfl_sync(FULL, re, sA1), y1 = __shfl_sync(FULL, im, sA1);
            float x2 = __shfl_sync(FULL, re, sA2), y2 = __shfl_sync(FULL, im, sA2);
            float x3 = __shfl_sync(FULL, re, sA3), y3 = __shfl_sync(FULL, im, sA3);
            float pr0 = e0.x * x0; pr0 = fmaf(-e0.y, y0, pr0);
            float pr1 = e0.z * x1; pr1 = fmaf(-e0.w, y1, pr1);
            float pr2 = e1.x * x2; pr2 = fmaf(-e1.y, y2, pr2);
            float pr3 = e1.z * x3; pr3 = fmaf(-e1.w, y3, pr3);
            float pi0 = e0.x * y0; pi0 = fmaf(e0.y, x0, pi0);
            float pi1 = e0.z * y1; pi1 = fmaf(e0.w, x1, pi1);
            float pi2 = e1.x * y2; pi2 = fmaf(e1.y, x2, pi2);
            float pi3 = e1.z * y3; pi3 = fmaf(e1.w, x3, pi3);
            re = (pr0 + pr1) + (pr2 + pr3);
            im = (pi0 + pi1) + (pi2 + pi3);
        }
        {   // step B: 4x4 on qubits (2,3)
            int base = (d * 8 + 4 + rBi) * 2;
            float4 e0 = Rows[base], e1 = Rows[base + 1];
            float x0 = __shfl_sync(FULL, re, sB0), y0 = __shfl_sync(FULL, im, sB0);
            float x1 = __shfl_sync(FULL, re, sB1), y1 = __shfl_sync(FULL, im, sB1);
            float x2 = __shfl_sync(FULL, re, sB2), y2 = __shfl_sync(FULL, im, sB2);
            float x3 = __shfl_sync(FULL, re, sB3), y3 = __shfl_sync(FULL, im, sB3);
            float pr0 = e0.x * x0; pr0 = fmaf(-e0.y, y0, pr0);
            float pr1 = e0.z * x1; pr1 = fmaf(-e0.w, y1, pr1);
            float pr2 = e1.x * x2; pr2 = fmaf(-e1.y, y2, pr2);
            float pr3 = e1.z * x3; pr3 = fmaf(-e1.w, y3, pr3);
            float pi0 = e0.x * y0; pi0 = fmaf(e0.y, x0, pi0);
            float pi1 = e0.z * y1; pi1 = fmaf(e0.w, x1, pi1);
            float pi2 = e1.x * y2; pi2 = fmaf(e1.y, x2, pi2);
            float pi3 = e1.z * y3; pi3 = fmaf(e1.w, x3, pi3);
            re = (pr0 + pr1) + (pr2 + pr3);
            im = (pi0 + pi1) + (pi2 + pi3);
        }
    }

    // ---- outputs: |amp[0]|^2, |amp[2]|^2, |amp[15]|^2 ----
    float prob = fmaf(re, re, im * im);
    if (l == 0)  out[0] = prob;
    if (l == 2)  out[1] = prob;
    if (l == 15) out[2] = prob;
}

extern "C" void kernel_launch(void* const* d_in, const int* in_sizes, int n_in,
                              void* d_out, int out_size) {
    const float* psi  = (const float*)d_in[0];
    const float* ring = (const float*)d_in[1];
    const float* prx  = (const float*)d_in[2];
    const float* pry  = (const float*)d_in[3];
    const float* prz  = (const float*)d_in[4];
    vqc_kernel<<<1, 128>>>(psi, ring, prx, pry, prz, (float*)d_out);
}